// round 2
// baseline (speedup 1.0000x reference)
#include <cuda_runtime.h>
#include <cuda_fp16.h>
#include <cstdint>

#define E_NUM 32
#define DK 1024
#define DN 1024
#define BM 128
#define BN 128
#define KC 64            /* fp16 per K-chunk = 128 bytes/row */
#define NCHUNK (DK / KC) /* 16 */
#define STAGES 3
#define MT_CAP 1152
#define TMAX 131072LL

/* ---------------- scratch (device globals; no allocation APIs) -------------- */
static __device__ __align__(1024) __half g_Ah[TMAX * DK];                   /* 256 MB */
static __device__ __align__(1024) __half g_Wh[(long long)E_NUM * DN * DK];  /* 64 MB  */
static __device__ int g_tile_expert[MT_CAP];
static __device__ int g_tile_row[MT_CAP];
static __device__ int g_tile_nrows[MT_CAP];
static __device__ int g_num_mtiles;

/* ---------------- helpers ---------------- */
static __device__ __forceinline__ uint32_t smem_u32(const void* p) {
    uint32_t a;
    asm("{ .reg .u64 t; cvta.to.shared.u64 t, %1; cvt.u32.u64 %0, t; }" : "=r"(a) : "l"(p));
    return a;
}
static __device__ __forceinline__ void cp16(uint32_t dst, const void* src, int src_size) {
    asm volatile("cp.async.cg.shared.global [%0], [%1], 16, %2;\n"
                 :: "r"(dst), "l"(src), "r"(src_size));
}
#define CP_COMMIT()  asm volatile("cp.async.commit_group;\n" ::: "memory")

#define LDSM_X4(r0, r1, r2, r3, addr) \
    asm volatile("ldmatrix.sync.aligned.m8n8.x4.shared.b16 {%0,%1,%2,%3}, [%4];" \
                 : "=r"(r0), "=r"(r1), "=r"(r2), "=r"(r3) : "r"(addr))

#define MMA16816(c0, c1, c2, c3, a0, a1, a2, a3, b0, b1) \
    asm volatile("mma.sync.aligned.m16n8k16.row.col.f32.f16.f16.f32 " \
                 "{%0,%1,%2,%3}, {%4,%5,%6,%7}, {%8,%9}, {%0,%1,%2,%3};" \
                 : "+f"(c0), "+f"(c1), "+f"(c2), "+f"(c3) \
                 : "r"(a0), "r"(a1), "r"(a2), "r"(a3), "r"(b0), "r"(b1))

/* ---------------- pre-pass kernels ---------------- */
__global__ void cvtA_kernel(const float4* __restrict__ src, long long n4) {
    long long i = (long long)blockIdx.x * blockDim.x + threadIdx.x;
    long long stride = (long long)gridDim.x * blockDim.x;
    uint2* dst = reinterpret_cast<uint2*>(g_Ah);
    for (; i < n4; i += stride) {
        float4 v = src[i];
        __half2 h0 = __floats2half2_rn(v.x, v.y);
        __half2 h1 = __floats2half2_rn(v.z, v.w);
        uint2 u;
        u.x = *reinterpret_cast<uint32_t*>(&h0);
        u.y = *reinterpret_cast<uint32_t*>(&h1);
        dst[i] = u;
    }
}
__global__ void cvtW_kernel(const float4* __restrict__ src, long long n4) {
    long long i = (long long)blockIdx.x * blockDim.x + threadIdx.x;
    long long stride = (long long)gridDim.x * blockDim.x;
    uint2* dst = reinterpret_cast<uint2*>(g_Wh);
    for (; i < n4; i += stride) {
        float4 v = src[i];
        __half2 h0 = __floats2half2_rn(v.x, v.y);
        __half2 h1 = __floats2half2_rn(v.z, v.w);
        uint2 u;
        u.x = *reinterpret_cast<uint32_t*>(&h0);
        u.y = *reinterpret_cast<uint32_t*>(&h1);
        dst[i] = u;
    }
}

/* Build tile table. Handles expert_frequency delivered as int32 OR int64:
   if sum of first 32 int32 words != T, treat buffer as int64. */
__global__ void build_tiles_kernel(const int* __restrict__ ef, int T_tokens) {
    if (threadIdx.x != 0 || blockIdx.x != 0) return;
    long long s = 0;
    for (int i = 0; i < E_NUM; i++) s += ef[i];
    bool is64 = (s != (long long)T_tokens);
    long long off = 0;
    int t = 0;
    for (int e = 0; e < E_NUM; e++) {
        long long c;
        if (is64)
            c = (long long)(unsigned)ef[2 * e] | ((long long)ef[2 * e + 1] << 32);
        else
            c = ef[e];
        for (long long m = 0; m < c; m += BM) {
            long long rem = c - m;
            g_tile_expert[t] = e;
            g_tile_row[t]    = (int)(off + m);
            g_tile_nrows[t]  = (int)(rem < BM ? rem : BM);
            t++;
        }
        off += c;
    }
    g_num_mtiles = t;
}

/* ---------------- main grouped-GEMM kernel (mma.sync fp16) ----------------
   Tile 128x128, K-chunk 64 (128B rows, XOR-16 swizzle), 3-stage cp.async.
   8 warps: warp_m = wid>>1 (4 x 32 rows), warp_n = wid&1 (2 x 64 cols).      */

#define STAGE_BYTES 32768              /* A 16KB + B 16KB */
#define SMEM_TOTAL  (STAGES * STAGE_BYTES)

static __device__ __forceinline__ void load_stage(
    int c, int slot, uint32_t smem_base,
    const __half* __restrict__ gA, const __half* __restrict__ gB,
    int a_sz, int tid)
{
    /* thread t: A row = t>>1, chunks (t&1)*4 .. +3 ; same for B */
    const int row  = tid >> 1;
    const int j0   = (tid & 1) * 4;
    const uint32_t xorv = (uint32_t)(row & 7) * 16u;
    uint32_t sA = smem_base + (uint32_t)slot * STAGE_BYTES + (uint32_t)row * 128u;
    uint32_t sB = sA + 16384u;
    const char* srcA = (const char*)(gA + (size_t)row * DK + (size_t)c * KC) + j0 * 16;
    const char* srcB = (const char*)(gB + (size_t)row * DK + (size_t)c * KC) + j0 * 16;
#pragma unroll
    for (int j = 0; j < 4; j++) {
        uint32_t col = ((uint32_t)(j0 + j) * 16u) ^ xorv;
        cp16(sA + col, srcA + j * 16, a_sz);
        cp16(sB + col, srcB + j * 16, 16);
    }
    CP_COMMIT();
}

__global__ void __launch_bounds__(256, 2) gemm_kernel(
    const float* __restrict__ bias, float* __restrict__ out, int T_tokens)
{
    extern __shared__ __align__(1024) char smem[];
    const int nt = blockIdx.x;           /* fast dim: 8 N-tiles co-resident */
    const int mt = blockIdx.y;
    if (mt >= g_num_mtiles) return;

    const int e     = g_tile_expert[mt];
    const int row0  = g_tile_row[mt];
    const int nrows = g_tile_nrows[mt];

    const uint32_t smem_base = smem_u32(smem);
    const int tid  = threadIdx.x;
    const int lane = tid & 31;
    const int wid  = tid >> 5;
    const int warp_m = wid >> 1;         /* 0..3 */
    const int warp_n = wid & 1;          /* 0..1 */

    /* global pointers for this CTA's loads */
    const int arow = tid >> 1;           /* row this thread loads for A */
    const int a_sz = (row0 + arow < T_tokens) ? 16 : 0;
    const __half* gA = g_Ah + (size_t)row0 * DK;
    const __half* gB = g_Wh + ((size_t)e * DN + (size_t)nt * BN) * DK;

    /* ldmatrix per-lane address precompute (byte offsets within a stage) */
    uint32_t aRow[2], aXor[2];
#pragma unroll
    for (int mf = 0; mf < 2; mf++) {
        int r = warp_m * 32 + mf * 16 + (lane & 15);
        aRow[mf] = (uint32_t)r * 128u;
        aXor[mf] = (uint32_t)(r & 7) * 16u;
    }
    const uint32_t aHi = (uint32_t)((lane >> 4) & 1) * 16u;

    uint32_t bRow[4], bXor[4];
#pragma unroll
    for (int g = 0; g < 4; g++) {
        int r = warp_n * 64 + g * 16 + (lane & 7) + (((lane >> 4) & 1) << 3);
        bRow[g] = (uint32_t)r * 128u;
        bXor[g] = (uint32_t)(r & 7) * 16u;
    }
    const uint32_t bHi = (uint32_t)((lane >> 3) & 1) * 16u;

    float acc[2][8][4];
#pragma unroll
    for (int mf = 0; mf < 2; mf++)
#pragma unroll
        for (int nf = 0; nf < 8; nf++)
#pragma unroll
            for (int k = 0; k < 4; k++) acc[mf][nf][k] = 0.0f;

    /* prologue */
    load_stage(0, 0, smem_base, gA, gB, a_sz, tid);
    load_stage(1, 1, smem_base, gA, gB, a_sz, tid);

#pragma unroll 1
    for (int c = 0; c < NCHUNK; c++) {
        if (c < NCHUNK - 1) asm volatile("cp.async.wait_group 1;" ::: "memory");
        else                asm volatile("cp.async.wait_group 0;" ::: "memory");
        __syncthreads();

        if (c + 2 < NCHUNK) {
            load_stage(c + 2, (c + 2) % STAGES, smem_base, gA, gB, a_sz, tid);
        }

        const uint32_t sA = smem_base + (uint32_t)(c % STAGES) * STAGE_BYTES;
        const uint32_t sB = sA + 16384u;

#pragma unroll
        for (int ks = 0; ks < 4; ks++) {
            const uint32_t kb = (uint32_t)ks * 32u;
            uint32_t a[2][4];
#pragma unroll
            for (int mf = 0; mf < 2; mf++) {
                uint32_t addr = sA + aRow[mf] + ((kb + aHi) ^ aXor[mf]);
                LDSM_X4(a[mf][0], a[mf][1], a[mf][2], a[mf][3], addr);
            }
            uint32_t b[4][4];
#pragma unroll
            for (int g = 0; g < 4; g++) {
                uint32_t addr = sB + bRow[g] + ((kb + bHi) ^ bXor[g]);
                LDSM_X4(b[g][0], b[g][1], b[g][2], b[g][3], addr);
            }
#pragma unroll
            for (int mf = 0; mf < 2; mf++) {
#pragma unroll
                for (int nf = 0; nf < 8; nf++) {
                    const int g  = nf >> 1;
                    const int hi = (nf & 1) * 2;
                    MMA16816(acc[mf][nf][0], acc[mf][nf][1], acc[mf][nf][2], acc[mf][nf][3],
                             a[mf][0], a[mf][1], a[mf][2], a[mf][3],
                             b[g][hi], b[g][hi + 1]);
                }
            }
        }
    }

    /* epilogue: out = acc + bias */
    const int colBase = nt * BN + warp_n * 64 + (lane & 3) * 2;
    const float* brow = bias + (size_t)e * DN;
#pragma unroll
    for (int mf = 0; mf < 2; mf++) {
#pragma unroll
        for (int half = 0; half < 2; half++) {
            const int r = warp_m * 32 + mf * 16 + (lane >> 2) + half * 8;
            if (r < nrows) {
                float* orow = out + (size_t)(row0 + r) * DN;
#pragma unroll
                for (int nf = 0; nf < 8; nf++) {
                    const int col = colBase + nf * 8;
                    float2 v;
                    v.x = acc[mf][nf][half * 2 + 0] + brow[col];
                    v.y = acc[mf][nf][half * 2 + 1] + brow[col + 1];
                    *(float2*)(orow + col) = v;
                }
            }
        }
    }
}

/* ---------------- host launcher ---------------- */
extern "C" void kernel_launch(void* const* d_in, const int* in_sizes, int n_in,
                              void* d_out, int out_size)
{
    const float* x    = (const float*)d_in[0];
    const int*   ef   = (const int*)d_in[1];
    const float* w    = (const float*)d_in[2];
    const float* bias = (const float*)d_in[3];
    float* out = (float*)d_out;

    const long long T = (long long)in_sizes[0] / DK;

    const long long nA4 = T * DK / 4;
    cvtA_kernel<<<4096, 256>>>((const float4*)x, nA4);
    const long long nW4 = (long long)E_NUM * DN * DK / 4;
    cvtW_kernel<<<2048, 256>>>((const float4*)w, nW4);
    build_tiles_kernel<<<1, 32>>>(ef, (int)T);

    cudaFuncSetAttribute(gemm_kernel, cudaFuncAttributeMaxDynamicSharedMemorySize, SMEM_TOTAL);

    const int mt_max = (int)((T + BM - 1) / BM) + E_NUM;   /* upper bound on tiles */
    dim3 grid(DN / BN, (unsigned)mt_max);                  /* (8, ~1056) */
    gemm_kernel<<<grid, 256, SMEM_TOTAL>>>(bias, out, (int)T);
}